// round 7
// baseline (speedup 1.0000x reference)
#include <cuda_runtime.h>

// ---------------------------------------------------------------------------
// GATv2 forward, CSR + fused softmax/aggregate/pool.
//   gemm: 128x128 output tile, 8x8 per thread, K-tiles of 32 (33KB smem)
//   CSR build: hist -> 3-step multiblock scan -> fill
//   aggregate: WARP per dst node, float4 per lane; softmax without max-shift
//   (logits O(1); shift cancels exactly in alpha); fused bias+relu+pool.
// Shapes: N=50000, E=800000, D=128, H=4, C=32, HC=128, G=64.
// edge_index / batch_ids arrive as int32 (harness canonicalizes int64).
// ---------------------------------------------------------------------------

#define NMAX   50048
#define EMAX   800000
#define GMAX   256

__device__ float g_xl[(size_t)NMAX * 128];
__device__ float g_xr[(size_t)NMAX * 128];
__device__ int   g_cnt[NMAX];
__device__ int   g_rowptr[NMAX + 1];
__device__ int   g_cursor[NMAX];
__device__ int   g_csrc[EMAX];
__device__ int   g_bsum[64];
__device__ int   g_boff[64];
__device__ float g_pooled[GMAX * 128];

__device__ __forceinline__ int clampi(int v, int lo, int hi) {
    return v < lo ? lo : (v > hi ? hi : v);
}

// ---------------------------------------------------------------------------
__global__ void init_kernel(int n_nodes, int n_pool) {
    int i = blockIdx.x * blockDim.x + threadIdx.x;
    int stride = gridDim.x * blockDim.x;
    for (int idx = i; idx < n_nodes; idx += stride) g_cnt[idx] = 0;
    for (int idx = i; idx < n_pool; idx += stride) g_pooled[idx] = 0.f;
}

// ---------------------------------------------------------------------------
__global__ void hist_kernel(const int* __restrict__ ei, int E, int N) {
    int i = blockIdx.x * blockDim.x + threadIdx.x;
    int stride = gridDim.x * blockDim.x;
    for (int e = i; e < E; e += stride)
        atomicAdd(&g_cnt[clampi(ei[E + e], 0, N - 1)], 1);
}

// scan1: per-1024-chunk block scan; local exclusive prefix + chunk total.
__global__ void __launch_bounds__(1024) scan1_kernel(int N) {
    __shared__ int wsum[32];
    int base = blockIdx.x * 1024;
    int t = threadIdx.x, lane = t & 31, w = t >> 5;
    int v = (base + t < N) ? g_cnt[base + t] : 0;

    int x = v;
#pragma unroll
    for (int off = 1; off < 32; off <<= 1) {
        int y = __shfl_up_sync(0xFFFFFFFFu, x, off);
        if (lane >= off) x += y;
    }
    if (lane == 31) wsum[w] = x;
    __syncthreads();
    if (w == 0) {
        int s = wsum[lane];
#pragma unroll
        for (int off = 1; off < 32; off <<= 1) {
            int y = __shfl_up_sync(0xFFFFFFFFu, s, off);
            if (lane >= off) s += y;
        }
        wsum[lane] = s;
    }
    __syncthreads();

    int excl = x - v + (w > 0 ? wsum[w - 1] : 0);
    if (base + t < N) g_rowptr[base + t] = excl;
    if (t == 1023) g_bsum[blockIdx.x] = excl + v;
}

// scan2: exclusive scan of up to 64 chunk totals.
__global__ void __launch_bounds__(64) scan2_kernel(int nb) {
    __shared__ int s[64];
    int t = threadIdx.x;
    int v = (t < nb) ? g_bsum[t] : 0;
    s[t] = v;
    __syncthreads();
#pragma unroll
    for (int off = 1; off < 64; off <<= 1) {
        int add = (t >= off) ? s[t - off] : 0;
        __syncthreads();
        s[t] += add;
        __syncthreads();
    }
    if (t < nb) g_boff[t] = s[t] - v;
}

// scan3: add chunk offsets; materialize rowptr + cursor.
__global__ void __launch_bounds__(1024) scan3_kernel(int N, int E) {
    int i = blockIdx.x * 1024 + threadIdx.x;
    if (i < N) {
        int r = g_rowptr[i] + g_boff[blockIdx.x];
        g_rowptr[i] = r;
        g_cursor[i] = r;
    }
    if (i == 0) g_rowptr[N] = E;
}

// ---------------------------------------------------------------------------
// GEMM: 128x128 output tile, 256 threads, 8x8 per thread, K-tiles of 32.
// As padded to 33 cols (conflict-free column reads); split-column B access
// (tx*4 and 64+tx*4) keeps float4 LDS phase-conflict-free.
// cb 0 -> Wl -> g_xl ; cb 1 -> Wr -> g_xr.
// ---------------------------------------------------------------------------
__global__ void __launch_bounds__(256) gemm_kernel(
    const float* __restrict__ x,
    const float* __restrict__ Wl,
    const float* __restrict__ Wr,
    int N)
{
    __shared__ float As[128 * 33];   // 16.5 KB
    __shared__ float Bs[32 * 128];   // 16 KB

    int cb   = blockIdx.x;
    int row0 = blockIdx.y * 128;
    const float* W   = cb ? Wr : Wl;
    float*       dst = cb ? g_xr : g_xl;
    int t = threadIdx.x;
    int tx = t & 15, ty = t >> 4;

    float acc[8][8];
#pragma unroll
    for (int i = 0; i < 8; i++)
#pragma unroll
        for (int j = 0; j < 8; j++) acc[i][j] = 0.f;

#pragma unroll
    for (int k0 = 0; k0 < 128; k0 += 32) {
        // A tile: 128 rows x 8 float4 loads -> padded scalar stores
#pragma unroll
        for (int i = 0; i < 4; i++) {
            int idx = i * 256 + t;          // 0..1023
            int r = idx >> 3, c4 = idx & 7;
            float4 v = make_float4(0.f, 0.f, 0.f, 0.f);
            if (row0 + r < N)
                v = *(const float4*)&x[(size_t)(row0 + r) * 128 + k0 + c4 * 4];
            float* d = &As[r * 33 + c4 * 4];
            d[0] = v.x; d[1] = v.y; d[2] = v.z; d[3] = v.w;
        }
        // B tile: 32 rows x 32 float4
#pragma unroll
        for (int i = 0; i < 4; i++) {
            int idx = i * 256 + t;
            int k = idx >> 5, j4 = idx & 31;
            *(float4*)&Bs[k * 128 + j4 * 4] = *(const float4*)&W[(k0 + k) * 128 + j4 * 4];
        }
        __syncthreads();

#pragma unroll
        for (int k = 0; k < 32; k++) {
            float a[8];
#pragma unroll
            for (int i = 0; i < 8; i++) a[i] = As[(ty * 8 + i) * 33 + k];
            float4 b0 = *(float4*)&Bs[k * 128 + tx * 4];
            float4 b1 = *(float4*)&Bs[k * 128 + 64 + tx * 4];
#pragma unroll
            for (int i = 0; i < 8; i++) {
                acc[i][0] += a[i] * b0.x; acc[i][1] += a[i] * b0.y;
                acc[i][2] += a[i] * b0.z; acc[i][3] += a[i] * b0.w;
                acc[i][4] += a[i] * b1.x; acc[i][5] += a[i] * b1.y;
                acc[i][6] += a[i] * b1.z; acc[i][7] += a[i] * b1.w;
            }
        }
        __syncthreads();
    }

#pragma unroll
    for (int i = 0; i < 8; i++) {
        int row = row0 + ty * 8 + i;
        if (row < N) {
            *(float4*)&dst[(size_t)row * 128 + tx * 4] =
                make_float4(acc[i][0], acc[i][1], acc[i][2], acc[i][3]);
            *(float4*)&dst[(size_t)row * 128 + 64 + tx * 4] =
                make_float4(acc[i][4], acc[i][5], acc[i][6], acc[i][7]);
        }
    }
}

// ---------------------------------------------------------------------------
__global__ void fill_kernel(const int* __restrict__ ei, int E, int N) {
    int i = blockIdx.x * blockDim.x + threadIdx.x;
    int stride = gridDim.x * blockDim.x;
    for (int e = i; e < E; e += stride) {
        int d = clampi(ei[E + e], 0, N - 1);
        int pos = atomicAdd(&g_cursor[d], 1);
        g_csrc[pos] = clampi(ei[e], 0, N - 1);
    }
}

// ---------------------------------------------------------------------------
// Aggregate: ONE WARP per dst node; lane owns 4 channels (float4).
// Head h = lanes h*8..h*8+7; 3 butterfly shuffles reduce the head logit.
// Softmax without max-shift (cancels in alpha). Fused bias+relu+atomicMax pool.
// ---------------------------------------------------------------------------
__device__ __forceinline__ float head_sum8(float v) {
    v += __shfl_xor_sync(0xFFFFFFFFu, v, 1);
    v += __shfl_xor_sync(0xFFFFFFFFu, v, 2);
    v += __shfl_xor_sync(0xFFFFFFFFu, v, 4);
    return v;
}

__global__ void __launch_bounds__(256) aggregate_kernel(
    const float* __restrict__ att,
    const float* __restrict__ bias,
    const int* __restrict__ batch,
    int N)
{
    int d    = (blockIdx.x * 256 + threadIdx.x) >> 5;
    int lane = threadIdx.x & 31;
    if (d >= N) return;

    float4 xr = *(const float4*)&g_xr[(size_t)d * 128 + lane * 4];
    float4 aw = *(const float4*)&att[lane * 4];

    // self loop
    float4 xs = *(const float4*)&g_xl[(size_t)d * 128 + lane * 4];
    float vx = xs.x + xr.x; vx = vx > 0.f ? vx : 0.2f * vx;
    float vy = xs.y + xr.y; vy = vy > 0.f ? vy : 0.2f * vy;
    float vz = xs.z + xr.z; vz = vz > 0.f ? vz : 0.2f * vz;
    float vw = xs.w + xr.w; vw = vw > 0.f ? vw : 0.2f * vw;
    float tq = head_sum8(vx * aw.x + vy * aw.y + vz * aw.z + vw * aw.w);
    float ex = __expf(tq);
    float denom = ex;
    float4 acc = make_float4(ex * xs.x, ex * xs.y, ex * xs.z, ex * xs.w);

    int p    = g_rowptr[d];
    int pend = g_rowptr[d + 1];

    for (; p + 1 < pend; p += 2) {
        int s0 = g_csrc[p], s1 = g_csrc[p + 1];
        float4 x0 = *(const float4*)&g_xl[(size_t)s0 * 128 + lane * 4];
        float4 x1 = *(const float4*)&g_xl[(size_t)s1 * 128 + lane * 4];

        float a0 = x0.x + xr.x; a0 = a0 > 0.f ? a0 : 0.2f * a0;
        float b0 = x0.y + xr.y; b0 = b0 > 0.f ? b0 : 0.2f * b0;
        float c0 = x0.z + xr.z; c0 = c0 > 0.f ? c0 : 0.2f * c0;
        float d0 = x0.w + xr.w; d0 = d0 > 0.f ? d0 : 0.2f * d0;
        float t0 = a0 * aw.x + b0 * aw.y + c0 * aw.z + d0 * aw.w;

        float a1 = x1.x + xr.x; a1 = a1 > 0.f ? a1 : 0.2f * a1;
        float b1 = x1.y + xr.y; b1 = b1 > 0.f ? b1 : 0.2f * b1;
        float c1 = x1.z + xr.z; c1 = c1 > 0.f ? c1 : 0.2f * c1;
        float d1 = x1.w + xr.w; d1 = d1 > 0.f ? d1 : 0.2f * d1;
        float t1 = a1 * aw.x + b1 * aw.y + c1 * aw.z + d1 * aw.w;

#pragma unroll
        for (int m = 1; m <= 4; m <<= 1) {
            t0 += __shfl_xor_sync(0xFFFFFFFFu, t0, m);
            t1 += __shfl_xor_sync(0xFFFFFFFFu, t1, m);
        }
        float e0 = __expf(t0), e1 = __expf(t1);
        denom += e0 + e1;
        acc.x += e0 * x0.x + e1 * x1.x;
        acc.y += e0 * x0.y + e1 * x1.y;
        acc.z += e0 * x0.z + e1 * x1.z;
        acc.w += e0 * x0.w + e1 * x1.w;
    }
    if (p < pend) {
        int s0 = g_csrc[p];
        float4 x0 = *(const float4*)&g_xl[(size_t)s0 * 128 + lane * 4];
        float a0 = x0.x + xr.x; a0 = a0 > 0.f ? a0 : 0.2f * a0;
        float b0 = x0.y + xr.y; b0 = b0 > 0.f ? b0 : 0.2f * b0;
        float c0 = x0.z + xr.z; c0 = c0 > 0.f ? c0 : 0.2f * c0;
        float d0 = x0.w + xr.w; d0 = d0 > 0.f ? d0 : 0.2f * d0;
        float t0 = head_sum8(a0 * aw.x + b0 * aw.y + c0 * aw.z + d0 * aw.w);
        float e0 = __expf(t0);
        denom += e0;
        acc.x += e0 * x0.x; acc.y += e0 * x0.y;
        acc.z += e0 * x0.z; acc.w += e0 * x0.w;
    }

    float4 bi = *(const float4*)&bias[lane * 4];
    float inv = 1.f / denom;
    float o0 = fmaxf(acc.x * inv + bi.x, 0.f);
    float o1 = fmaxf(acc.y * inv + bi.y, 0.f);
    float o2 = fmaxf(acc.z * inv + bi.z, 0.f);
    float o3 = fmaxf(acc.w * inv + bi.w, 0.f);

    int g = clampi(batch[d], 0, GMAX - 1);
    int* pp = (int*)&g_pooled[g * 128 + lane * 4];
    atomicMax(pp + 0, __float_as_int(o0));
    atomicMax(pp + 1, __float_as_int(o1));
    atomicMax(pp + 2, __float_as_int(o2));
    atomicMax(pp + 3, __float_as_int(o3));
}

// ---------------------------------------------------------------------------
__global__ void __launch_bounds__(128) mlp_kernel(
    const float* __restrict__ W,
    const float* __restrict__ b,
    float* __restrict__ out)
{
    __shared__ float pbuf[128];
    int j = threadIdx.x, g = blockIdx.x;
    pbuf[j] = g_pooled[g * 128 + j];
    __syncthreads();
    float acc = b[j];
#pragma unroll 8
    for (int k = 0; k < 128; k++)
        acc += pbuf[k] * W[k * 128 + j];
    out[g * 128 + j] = fmaxf(acc, 0.f);
}

// ---------------------------------------------------------------------------
extern "C" void kernel_launch(void* const* d_in, const int* in_sizes, int n_in,
                              void* d_out, int out_size)
{
    const float* x     = (const float*)d_in[0];
    const int*   ei    = (const int*)d_in[1];
    const int*   batch = (const int*)d_in[2];
    int base = (n_in >= 10) ? 4 : 3;
    const float* Wl   = (const float*)d_in[base + 0];
    const float* Wr   = (const float*)d_in[base + 1];
    const float* att  = (const float*)d_in[base + 2];
    const float* bias = (const float*)d_in[base + 3];
    const float* Wm   = (const float*)d_in[base + 4];
    const float* bm   = (const float*)d_in[base + 5];

    int N = in_sizes[0] / 128;
    int E = in_sizes[1] / 2;
    int G = out_size / 128;
    float* out = (float*)d_out;
    int nb = (N + 1023) / 1024;

    init_kernel<<<(N + 255) / 256, 256>>>(N, G * 128);                 // 0
    hist_kernel<<<592, 256>>>(ei, E, N);                               // 1
    scan1_kernel<<<nb, 1024>>>(N);                                     // 2

    dim3 ggrid(2, (N + 127) / 128);
    gemm_kernel<<<ggrid, 256>>>(x, Wl, Wr, N);                         // 3 (ncu captures idx 3)

    scan2_kernel<<<1, 64>>>(nb);                                       // 4
    scan3_kernel<<<nb, 1024>>>(N, E);                                  // 5
    fill_kernel<<<592, 256>>>(ei, E, N);                               // 6
    aggregate_kernel<<<(N * 32 + 255) / 256, 256>>>(att, bias, batch, N); // 7
    mlp_kernel<<<G, 128>>>(Wm, bm, out);                               // 8
}

// round 8
// speedup vs baseline: 1.2624x; 1.2624x over previous
#include <cuda_runtime.h>

// ---------------------------------------------------------------------------
// GATv2 forward, CSR + fused softmax/aggregate/pool.
//   gemm: 64x64 tile, 4x4/thread (high occupancy: ~6 blocks/SM — the 128x128
//         8x8 variant hit 144 regs -> 1 block/SM -> 12% occ -> 3x slower)
//   CSR build: hist -> 3-step multiblock scan -> fill
//   aggregate: WARP per dst node, float4 per lane; softmax without max-shift
//   (logits O(1); shift cancels exactly in alpha); fused bias+relu+pool.
// Shapes: N=50000, E=800000, D=128, H=4, C=32, HC=128, G=64.
// edge_index / batch_ids arrive as int32 (harness canonicalizes int64).
// ---------------------------------------------------------------------------

#define NMAX   50048
#define EMAX   800000
#define GMAX   256

__device__ float g_xl[(size_t)NMAX * 128];
__device__ float g_xr[(size_t)NMAX * 128];
__device__ int   g_cnt[NMAX];
__device__ int   g_rowptr[NMAX + 1];
__device__ int   g_cursor[NMAX];
__device__ int   g_csrc[EMAX];
__device__ int   g_bsum[64];
__device__ int   g_boff[64];
__device__ float g_pooled[GMAX * 128];

__device__ __forceinline__ int clampi(int v, int lo, int hi) {
    return v < lo ? lo : (v > hi ? hi : v);
}

// ---------------------------------------------------------------------------
__global__ void init_kernel(int n_nodes, int n_pool) {
    int i = blockIdx.x * blockDim.x + threadIdx.x;
    int stride = gridDim.x * blockDim.x;
    for (int idx = i; idx < n_nodes; idx += stride) g_cnt[idx] = 0;
    for (int idx = i; idx < n_pool; idx += stride) g_pooled[idx] = 0.f;
}

// ---------------------------------------------------------------------------
__global__ void hist_kernel(const int* __restrict__ ei, int E, int N) {
    int i = blockIdx.x * blockDim.x + threadIdx.x;
    int stride = gridDim.x * blockDim.x;
    for (int e = i; e < E; e += stride)
        atomicAdd(&g_cnt[clampi(ei[E + e], 0, N - 1)], 1);
}

// scan1: per-1024-chunk block scan; local exclusive prefix + chunk total.
__global__ void __launch_bounds__(1024) scan1_kernel(int N) {
    __shared__ int wsum[32];
    int base = blockIdx.x * 1024;
    int t = threadIdx.x, lane = t & 31, w = t >> 5;
    int v = (base + t < N) ? g_cnt[base + t] : 0;

    int x = v;
#pragma unroll
    for (int off = 1; off < 32; off <<= 1) {
        int y = __shfl_up_sync(0xFFFFFFFFu, x, off);
        if (lane >= off) x += y;
    }
    if (lane == 31) wsum[w] = x;
    __syncthreads();
    if (w == 0) {
        int s = wsum[lane];
#pragma unroll
        for (int off = 1; off < 32; off <<= 1) {
            int y = __shfl_up_sync(0xFFFFFFFFu, s, off);
            if (lane >= off) s += y;
        }
        wsum[lane] = s;
    }
    __syncthreads();

    int excl = x - v + (w > 0 ? wsum[w - 1] : 0);
    if (base + t < N) g_rowptr[base + t] = excl;
    if (t == 1023) g_bsum[blockIdx.x] = excl + v;
}

// scan2: exclusive scan of up to 64 chunk totals.
__global__ void __launch_bounds__(64) scan2_kernel(int nb) {
    __shared__ int s[64];
    int t = threadIdx.x;
    int v = (t < nb) ? g_bsum[t] : 0;
    s[t] = v;
    __syncthreads();
#pragma unroll
    for (int off = 1; off < 64; off <<= 1) {
        int add = (t >= off) ? s[t - off] : 0;
        __syncthreads();
        s[t] += add;
        __syncthreads();
    }
    if (t < nb) g_boff[t] = s[t] - v;
}

// scan3: add chunk offsets; materialize rowptr + cursor.
__global__ void __launch_bounds__(1024) scan3_kernel(int N, int E) {
    int i = blockIdx.x * 1024 + threadIdx.x;
    if (i < N) {
        int r = g_rowptr[i] + g_boff[blockIdx.x];
        g_rowptr[i] = r;
        g_cursor[i] = r;
    }
    if (i == 0) g_rowptr[N] = E;
}

// ---------------------------------------------------------------------------
// Tiled fp32 GEMM: 64x64 output tile of (x @ W), K=128 in 2 K-tiles of 64.
// 4x4 per thread, ~40 regs -> ~6 blocks/SM (48 warps) -> fma-bound.
// cb 0,1 -> Wl -> g_xl ; cb 2,3 -> Wr -> g_xr.
// ---------------------------------------------------------------------------
__global__ void __launch_bounds__(256) gemm_kernel(
    const float* __restrict__ x,
    const float* __restrict__ Wl,
    const float* __restrict__ Wr,
    int N)
{
    __shared__ float As[64][64];
    __shared__ float Bs[64][64];

    int cb   = blockIdx.x;
    int row0 = blockIdx.y * 64;
    const float* W   = (cb < 2) ? Wl : Wr;
    float*       dst = (cb < 2) ? g_xl : g_xr;
    int col0 = (cb & 1) * 64;
    int t = threadIdx.x;
    int tx = t & 15, ty = t >> 4;

    float acc[4][4] = {};

#pragma unroll
    for (int k0 = 0; k0 < 128; k0 += 64) {
#pragma unroll
        for (int i = 0; i < 4; i++) {
            int idx = t + i * 256;
            int r = idx >> 4, c4 = idx & 15;
            float4 v = make_float4(0.f, 0.f, 0.f, 0.f);
            if (row0 + r < N)
                v = *(const float4*)&x[(size_t)(row0 + r) * 128 + k0 + c4 * 4];
            *(float4*)&As[r][c4 * 4] = v;
        }
#pragma unroll
        for (int i = 0; i < 4; i++) {
            int idx = t + i * 256;
            int k = idx >> 4, j4 = idx & 15;
            *(float4*)&Bs[k][j4 * 4] = *(const float4*)&W[(k0 + k) * 128 + col0 + j4 * 4];
        }
        __syncthreads();

#pragma unroll 8
        for (int k = 0; k < 64; k++) {
            float a0 = As[ty * 4 + 0][k];
            float a1 = As[ty * 4 + 1][k];
            float a2 = As[ty * 4 + 2][k];
            float a3 = As[ty * 4 + 3][k];
            float4 b = *(float4*)&Bs[k][tx * 4];
            acc[0][0] += a0 * b.x; acc[0][1] += a0 * b.y; acc[0][2] += a0 * b.z; acc[0][3] += a0 * b.w;
            acc[1][0] += a1 * b.x; acc[1][1] += a1 * b.y; acc[1][2] += a1 * b.z; acc[1][3] += a1 * b.w;
            acc[2][0] += a2 * b.x; acc[2][1] += a2 * b.y; acc[2][2] += a2 * b.z; acc[2][3] += a2 * b.w;
            acc[3][0] += a3 * b.x; acc[3][1] += a3 * b.y; acc[3][2] += a3 * b.z; acc[3][3] += a3 * b.w;
        }
        __syncthreads();
    }

#pragma unroll
    for (int i = 0; i < 4; i++) {
        int row = row0 + ty * 4 + i;
        if (row < N) {
            float4 v = make_float4(acc[i][0], acc[i][1], acc[i][2], acc[i][3]);
            *(float4*)&dst[(size_t)row * 128 + col0 + tx * 4] = v;
        }
    }
}

// ---------------------------------------------------------------------------
__global__ void fill_kernel(const int* __restrict__ ei, int E, int N) {
    int i = blockIdx.x * blockDim.x + threadIdx.x;
    int stride = gridDim.x * blockDim.x;
    for (int e = i; e < E; e += stride) {
        int d = clampi(ei[E + e], 0, N - 1);
        int pos = atomicAdd(&g_cursor[d], 1);
        g_csrc[pos] = clampi(ei[e], 0, N - 1);
    }
}

// ---------------------------------------------------------------------------
// Aggregate: ONE WARP per dst node; lane owns 4 channels (float4).
// Head h = lanes h*8..h*8+7; 3 butterfly shuffles reduce the head logit.
// Softmax without max-shift (cancels in alpha). Fused bias+relu+atomicMax pool.
// ---------------------------------------------------------------------------
__device__ __forceinline__ float head_sum8(float v) {
    v += __shfl_xor_sync(0xFFFFFFFFu, v, 1);
    v += __shfl_xor_sync(0xFFFFFFFFu, v, 2);
    v += __shfl_xor_sync(0xFFFFFFFFu, v, 4);
    return v;
}

__global__ void __launch_bounds__(256) aggregate_kernel(
    const float* __restrict__ att,
    const float* __restrict__ bias,
    const int* __restrict__ batch,
    int N)
{
    int d    = (blockIdx.x * 256 + threadIdx.x) >> 5;
    int lane = threadIdx.x & 31;
    if (d >= N) return;

    float4 xr = *(const float4*)&g_xr[(size_t)d * 128 + lane * 4];
    float4 aw = *(const float4*)&att[lane * 4];

    // self loop
    float4 xs = *(const float4*)&g_xl[(size_t)d * 128 + lane * 4];
    float vx = xs.x + xr.x; vx = vx > 0.f ? vx : 0.2f * vx;
    float vy = xs.y + xr.y; vy = vy > 0.f ? vy : 0.2f * vy;
    float vz = xs.z + xr.z; vz = vz > 0.f ? vz : 0.2f * vz;
    float vw = xs.w + xr.w; vw = vw > 0.f ? vw : 0.2f * vw;
    float tq = head_sum8(vx * aw.x + vy * aw.y + vz * aw.z + vw * aw.w);
    float ex = __expf(tq);
    float denom = ex;
    float4 acc = make_float4(ex * xs.x, ex * xs.y, ex * xs.z, ex * xs.w);

    int p    = g_rowptr[d];
    int pend = g_rowptr[d + 1];

    for (; p + 1 < pend; p += 2) {
        int s0 = g_csrc[p], s1 = g_csrc[p + 1];
        float4 x0 = *(const float4*)&g_xl[(size_t)s0 * 128 + lane * 4];
        float4 x1 = *(const float4*)&g_xl[(size_t)s1 * 128 + lane * 4];

        float a0 = x0.x + xr.x; a0 = a0 > 0.f ? a0 : 0.2f * a0;
        float b0 = x0.y + xr.y; b0 = b0 > 0.f ? b0 : 0.2f * b0;
        float c0 = x0.z + xr.z; c0 = c0 > 0.f ? c0 : 0.2f * c0;
        float d0 = x0.w + xr.w; d0 = d0 > 0.f ? d0 : 0.2f * d0;
        float t0 = a0 * aw.x + b0 * aw.y + c0 * aw.z + d0 * aw.w;

        float a1 = x1.x + xr.x; a1 = a1 > 0.f ? a1 : 0.2f * a1;
        float b1 = x1.y + xr.y; b1 = b1 > 0.f ? b1 : 0.2f * b1;
        float c1 = x1.z + xr.z; c1 = c1 > 0.f ? c1 : 0.2f * c1;
        float d1 = x1.w + xr.w; d1 = d1 > 0.f ? d1 : 0.2f * d1;
        float t1 = a1 * aw.x + b1 * aw.y + c1 * aw.z + d1 * aw.w;

#pragma unroll
        for (int m = 1; m <= 4; m <<= 1) {
            t0 += __shfl_xor_sync(0xFFFFFFFFu, t0, m);
            t1 += __shfl_xor_sync(0xFFFFFFFFu, t1, m);
        }
        float e0 = __expf(t0), e1 = __expf(t1);
        denom += e0 + e1;
        acc.x += e0 * x0.x + e1 * x1.x;
        acc.y += e0 * x0.y + e1 * x1.y;
        acc.z += e0 * x0.z + e1 * x1.z;
        acc.w += e0 * x0.w + e1 * x1.w;
    }
    if (p < pend) {
        int s0 = g_csrc[p];
        float4 x0 = *(const float4*)&g_xl[(size_t)s0 * 128 + lane * 4];
        float a0 = x0.x + xr.x; a0 = a0 > 0.f ? a0 : 0.2f * a0;
        float b0 = x0.y + xr.y; b0 = b0 > 0.f ? b0 : 0.2f * b0;
        float c0 = x0.z + xr.z; c0 = c0 > 0.f ? c0 : 0.2f * c0;
        float d0 = x0.w + xr.w; d0 = d0 > 0.f ? d0 : 0.2f * d0;
        float t0 = head_sum8(a0 * aw.x + b0 * aw.y + c0 * aw.z + d0 * aw.w);
        float e0 = __expf(t0);
        denom += e0;
        acc.x += e0 * x0.x; acc.y += e0 * x0.y;
        acc.z += e0 * x0.z; acc.w += e0 * x0.w;
    }

    float4 bi = *(const float4*)&bias[lane * 4];
    float inv = 1.f / denom;
    float o0 = fmaxf(acc.x * inv + bi.x, 0.f);
    float o1 = fmaxf(acc.y * inv + bi.y, 0.f);
    float o2 = fmaxf(acc.z * inv + bi.z, 0.f);
    float o3 = fmaxf(acc.w * inv + bi.w, 0.f);

    int g = clampi(batch[d], 0, GMAX - 1);
    int* pp = (int*)&g_pooled[g * 128 + lane * 4];
    atomicMax(pp + 0, __float_as_int(o0));
    atomicMax(pp + 1, __float_as_int(o1));
    atomicMax(pp + 2, __float_as_int(o2));
    atomicMax(pp + 3, __float_as_int(o3));
}

// ---------------------------------------------------------------------------
__global__ void __launch_bounds__(128) mlp_kernel(
    const float* __restrict__ W,
    const float* __restrict__ b,
    float* __restrict__ out)
{
    __shared__ float pbuf[128];
    int j = threadIdx.x, g = blockIdx.x;
    pbuf[j] = g_pooled[g * 128 + j];
    __syncthreads();
    float acc = b[j];
#pragma unroll 8
    for (int k = 0; k < 128; k++)
        acc += pbuf[k] * W[k * 128 + j];
    out[g * 128 + j] = fmaxf(acc, 0.f);
}

// ---------------------------------------------------------------------------
extern "C" void kernel_launch(void* const* d_in, const int* in_sizes, int n_in,
                              void* d_out, int out_size)
{
    const float* x     = (const float*)d_in[0];
    const int*   ei    = (const int*)d_in[1];
    const int*   batch = (const int*)d_in[2];
    int base = (n_in >= 10) ? 4 : 3;
    const float* Wl   = (const float*)d_in[base + 0];
    const float* Wr   = (const float*)d_in[base + 1];
    const float* att  = (const float*)d_in[base + 2];
    const float* bias = (const float*)d_in[base + 3];
    const float* Wm   = (const float*)d_in[base + 4];
    const float* bm   = (const float*)d_in[base + 5];

    int N = in_sizes[0] / 128;
    int E = in_sizes[1] / 2;
    int G = out_size / 128;
    float* out = (float*)d_out;
    int nb = (N + 1023) / 1024;

    init_kernel<<<(N + 255) / 256, 256>>>(N, G * 128);                 // 0
    hist_kernel<<<592, 256>>>(ei, E, N);                               // 1
    scan1_kernel<<<nb, 1024>>>(N);                                     // 2

    dim3 ggrid(4, (N + 63) / 64);
    gemm_kernel<<<ggrid, 256>>>(x, Wl, Wr, N);                         // 3 (ncu captures idx 3)

    scan2_kernel<<<1, 64>>>(nb);                                       // 4
    scan3_kernel<<<nb, 1024>>>(N, E);                                  // 5
    fill_kernel<<<592, 256>>>(ei, E, N);                               // 6
    aggregate_kernel<<<(N * 32 + 255) / 256, 256>>>(att, bias, batch, N); // 7
    mlp_kernel<<<G, 128>>>(Wm, bm, out);                               // 8
}

// round 9
// speedup vs baseline: 1.3905x; 1.1014x over previous
#include <cuda_runtime.h>

// ---------------------------------------------------------------------------
// GATv2 forward, CSR + fused softmax/aggregate/pool.
//   gemm: 64x64 tile, 4x4/thread, A-tile stored TRANSPOSED (As_T[k][row],
//         pitch 68) so the per-k A read is one LDS.128 -> half the L1
//         wavefronts of the row-major version (which measured L1=85%).
//   aggregate: BLOCK per dst node (128 thr) — measured 47us faster than the
//         warp-per-node variant (4x outstanding-load parallelism per node).
//   CSR build: hist -> 3-step multiblock scan -> fill.
// Shapes: N=50000, E=800000, D=128, H=4, C=32, HC=128, G=64.
// edge_index / batch_ids arrive as int32 (harness canonicalizes int64).
// ---------------------------------------------------------------------------

#define NMAX   50048
#define EMAX   800000
#define GMAX   256

__device__ float g_xl[(size_t)NMAX * 128];
__device__ float g_xr[(size_t)NMAX * 128];
__device__ int   g_cnt[NMAX];
__device__ int   g_rowptr[NMAX + 1];
__device__ int   g_cursor[NMAX];
__device__ int   g_csrc[EMAX];
__device__ int   g_bsum[64];
__device__ int   g_boff[64];
__device__ float g_pooled[GMAX * 128];

__device__ __forceinline__ int clampi(int v, int lo, int hi) {
    return v < lo ? lo : (v > hi ? hi : v);
}

// ---------------------------------------------------------------------------
__global__ void init_kernel(int n_nodes, int n_pool) {
    int i = blockIdx.x * blockDim.x + threadIdx.x;
    int stride = gridDim.x * blockDim.x;
    for (int idx = i; idx < n_nodes; idx += stride) g_cnt[idx] = 0;
    for (int idx = i; idx < n_pool; idx += stride) g_pooled[idx] = 0.f;
}

// ---------------------------------------------------------------------------
__global__ void hist_kernel(const int* __restrict__ ei, int E, int N) {
    int i = blockIdx.x * blockDim.x + threadIdx.x;
    int stride = gridDim.x * blockDim.x;
    for (int e = i; e < E; e += stride)
        atomicAdd(&g_cnt[clampi(ei[E + e], 0, N - 1)], 1);
}

// scan1: per-1024-chunk block scan; local exclusive prefix + chunk total.
__global__ void __launch_bounds__(1024) scan1_kernel(int N) {
    __shared__ int wsum[32];
    int base = blockIdx.x * 1024;
    int t = threadIdx.x, lane = t & 31, w = t >> 5;
    int v = (base + t < N) ? g_cnt[base + t] : 0;

    int x = v;
#pragma unroll
    for (int off = 1; off < 32; off <<= 1) {
        int y = __shfl_up_sync(0xFFFFFFFFu, x, off);
        if (lane >= off) x += y;
    }
    if (lane == 31) wsum[w] = x;
    __syncthreads();
    if (w == 0) {
        int s = wsum[lane];
#pragma unroll
        for (int off = 1; off < 32; off <<= 1) {
            int y = __shfl_up_sync(0xFFFFFFFFu, s, off);
            if (lane >= off) s += y;
        }
        wsum[lane] = s;
    }
    __syncthreads();

    int excl = x - v + (w > 0 ? wsum[w - 1] : 0);
    if (base + t < N) g_rowptr[base + t] = excl;
    if (t == 1023) g_bsum[blockIdx.x] = excl + v;
}

// scan2: exclusive scan of up to 64 chunk totals.
__global__ void __launch_bounds__(64) scan2_kernel(int nb) {
    __shared__ int s[64];
    int t = threadIdx.x;
    int v = (t < nb) ? g_bsum[t] : 0;
    s[t] = v;
    __syncthreads();
#pragma unroll
    for (int off = 1; off < 64; off <<= 1) {
        int add = (t >= off) ? s[t - off] : 0;
        __syncthreads();
        s[t] += add;
        __syncthreads();
    }
    if (t < nb) g_boff[t] = s[t] - v;
}

// scan3: add chunk offsets; materialize rowptr + cursor.
__global__ void __launch_bounds__(1024) scan3_kernel(int N, int E) {
    int i = blockIdx.x * 1024 + threadIdx.x;
    if (i < N) {
        int r = g_rowptr[i] + g_boff[blockIdx.x];
        g_rowptr[i] = r;
        g_cursor[i] = r;
    }
    if (i == 0) g_rowptr[N] = E;
}

// ---------------------------------------------------------------------------
// GEMM: 64x64 output tile, 4x4/thread, K=128 in 2 K-tiles of 64.
// A-tile stored transposed: As_T[k][row], pitch 68 floats (272B = 17*16B,
// keeps float4 loads aligned; 68 mod 32-banks = 4 -> store conflicts <= 2-way).
// Per k-step per thread: 1 LDS.128 (A, 4 rows) + 1 LDS.128 (B, 4 cols).
// cb 0,1 -> Wl -> g_xl ; cb 2,3 -> Wr -> g_xr.
// ---------------------------------------------------------------------------
#define APITCH 68

__global__ void __launch_bounds__(256, 4) gemm_kernel(
    const float* __restrict__ x,
    const float* __restrict__ Wl,
    const float* __restrict__ Wr,
    int N)
{
    __shared__ float As[64 * APITCH];   // 17 KB, [k][row]
    __shared__ float Bs[64 * 64];       // 16 KB, [k][col]

    int cb   = blockIdx.x;
    int row0 = blockIdx.y * 64;
    const float* W   = (cb < 2) ? Wl : Wr;
    float*       dst = (cb < 2) ? g_xl : g_xr;
    int col0 = (cb & 1) * 64;
    int t = threadIdx.x;
    int tx = t & 15, ty = t >> 4;

    float acc[4][4] = {};

#pragma unroll
    for (int k0 = 0; k0 < 128; k0 += 64) {
        // A tile: load row-major float4 from gmem, store transposed (scalar).
#pragma unroll
        for (int i = 0; i < 4; i++) {
            int idx = t + i * 256;          // 0..1023
            int r = idx >> 4, c4 = idx & 15;
            float4 v = make_float4(0.f, 0.f, 0.f, 0.f);
            if (row0 + r < N)
                v = *(const float4*)&x[(size_t)(row0 + r) * 128 + k0 + c4 * 4];
            As[(c4 * 4 + 0) * APITCH + r] = v.x;
            As[(c4 * 4 + 1) * APITCH + r] = v.y;
            As[(c4 * 4 + 2) * APITCH + r] = v.z;
            As[(c4 * 4 + 3) * APITCH + r] = v.w;
        }
        // B tile: rows k0..k0+63, cols col0..col0+63
#pragma unroll
        for (int i = 0; i < 4; i++) {
            int idx = t + i * 256;
            int k = idx >> 4, j4 = idx & 15;
            *(float4*)&Bs[k * 64 + j4 * 4] = *(const float4*)&W[(k0 + k) * 128 + col0 + j4 * 4];
        }
        __syncthreads();

#pragma unroll 8
        for (int k = 0; k < 64; k++) {
            float4 a = *(float4*)&As[k * APITCH + ty * 4];
            float4 b = *(float4*)&Bs[k * 64 + tx * 4];
            acc[0][0] += a.x * b.x; acc[0][1] += a.x * b.y; acc[0][2] += a.x * b.z; acc[0][3] += a.x * b.w;
            acc[1][0] += a.y * b.x; acc[1][1] += a.y * b.y; acc[1][2] += a.y * b.z; acc[1][3] += a.y * b.w;
            acc[2][0] += a.z * b.x; acc[2][1] += a.z * b.y; acc[2][2] += a.z * b.z; acc[2][3] += a.z * b.w;
            acc[3][0] += a.w * b.x; acc[3][1] += a.w * b.y; acc[3][2] += a.w * b.z; acc[3][3] += a.w * b.w;
        }
        __syncthreads();
    }

#pragma unroll
    for (int i = 0; i < 4; i++) {
        int row = row0 + ty * 4 + i;
        if (row < N) {
            float4 v = make_float4(acc[i][0], acc[i][1], acc[i][2], acc[i][3]);
            *(float4*)&dst[(size_t)row * 128 + col0 + tx * 4] = v;
        }
    }
}

// ---------------------------------------------------------------------------
__global__ void fill_kernel(const int* __restrict__ ei, int E, int N) {
    int i = blockIdx.x * blockDim.x + threadIdx.x;
    int stride = gridDim.x * blockDim.x;
    for (int e = i; e < E; e += stride) {
        int d = clampi(ei[E + e], 0, N - 1);
        int pos = atomicAdd(&g_cursor[d], 1);
        g_csrc[pos] = clampi(ei[e], 0, N - 1);
    }
}

// ---------------------------------------------------------------------------
// Aggregate: one BLOCK (128 thr = 4 warps) per dst node. Warp h owns head h;
// thread j = h*32+c owns channel c. Softmax without max-shift (logits O(1);
// shift cancels exactly in alpha). Fused bias+relu+atomicMax pooling.
// ---------------------------------------------------------------------------
__device__ __forceinline__ float warp_sum(float v) {
    v += __shfl_xor_sync(0xFFFFFFFFu, v, 16);
    v += __shfl_xor_sync(0xFFFFFFFFu, v, 8);
    v += __shfl_xor_sync(0xFFFFFFFFu, v, 4);
    v += __shfl_xor_sync(0xFFFFFFFFu, v, 2);
    v += __shfl_xor_sync(0xFFFFFFFFu, v, 1);
    return v;
}

__global__ void __launch_bounds__(128) aggregate_kernel(
    const float* __restrict__ att,
    const float* __restrict__ bias,
    const int* __restrict__ batch,
    int N)
{
    int d = blockIdx.x;
    if (d >= N) return;
    int j = threadIdx.x;

    float xr_v  = g_xr[(size_t)d * 128 + j];
    float att_v = att[j];

    // self loop
    float xs = g_xl[(size_t)d * 128 + j];
    float v  = xs + xr_v;
    v = v > 0.f ? v : 0.2f * v;
    float logit = warp_sum(v * att_v);
    float ex    = __expf(logit);
    float denom = ex;
    float acc   = ex * xs;

    int p    = g_rowptr[d];
    int pend = g_rowptr[d + 1];

    for (; p + 1 < pend; p += 2) {
        int s0 = g_csrc[p], s1 = g_csrc[p + 1];
        float x0 = g_xl[(size_t)s0 * 128 + j];
        float x1 = g_xl[(size_t)s1 * 128 + j];
        float v0 = x0 + xr_v; v0 = v0 > 0.f ? v0 : 0.2f * v0;
        float v1 = x1 + xr_v; v1 = v1 > 0.f ? v1 : 0.2f * v1;
        float t0 = v0 * att_v, t1 = v1 * att_v;
#pragma unroll
        for (int m = 16; m >= 1; m >>= 1) {
            t0 += __shfl_xor_sync(0xFFFFFFFFu, t0, m);
            t1 += __shfl_xor_sync(0xFFFFFFFFu, t1, m);
        }
        float e0 = __expf(t0), e1 = __expf(t1);
        denom += e0 + e1;
        acc   += e0 * x0 + e1 * x1;
    }
    if (p < pend) {
        int s0 = g_csrc[p];
        float x0 = g_xl[(size_t)s0 * 128 + j];
        float v0 = x0 + xr_v; v0 = v0 > 0.f ? v0 : 0.2f * v0;
        float t0 = warp_sum(v0 * att_v);
        float e0 = __expf(t0);
        denom += e0;
        acc   += e0 * x0;
    }

    float o = fmaxf(acc / denom + bias[j], 0.f);
    int g = clampi(batch[d], 0, GMAX - 1);
    atomicMax((int*)&g_pooled[g * 128 + j], __float_as_int(o));
}

// ---------------------------------------------------------------------------
__global__ void __launch_bounds__(128) mlp_kernel(
    const float* __restrict__ W,
    const float* __restrict__ b,
    float* __restrict__ out)
{
    __shared__ float pbuf[128];
    int j = threadIdx.x, g = blockIdx.x;
    pbuf[j] = g_pooled[g * 128 + j];
    __syncthreads();
    float acc = b[j];
#pragma unroll 8
    for (int k = 0; k < 128; k++)
        acc += pbuf[k] * W[k * 128 + j];
    out[g * 128 + j] = fmaxf(acc, 0.f);
}

// ---------------------------------------------------------------------------
extern "C" void kernel_launch(void* const* d_in, const int* in_sizes, int n_in,
                              void* d_out, int out_size)
{
    const float* x     = (const float*)d_in[0];
    const int*   ei    = (const int*)d_in[1];
    const int*   batch = (const int*)d_in[2];
    int base = (n_in >= 10) ? 4 : 3;
    const float* Wl   = (const float*)d_in[base + 0];
    const float* Wr   = (const float*)d_in[base + 1];
    const float* att  = (const float*)d_in[base + 2];
    const float* bias = (const float*)d_in[base + 3];
    const float* Wm   = (const float*)d_in[base + 4];
    const float* bm   = (const float*)d_in[base + 5];

    int N = in_sizes[0] / 128;
    int E = in_sizes[1] / 2;
    int G = out_size / 128;
    float* out = (float*)d_out;
    int nb = (N + 1023) / 1024;

    init_kernel<<<(N + 255) / 256, 256>>>(N, G * 128);                 // 0
    hist_kernel<<<592, 256>>>(ei, E, N);                               // 1
    scan1_kernel<<<nb, 1024>>>(N);                                     // 2

    dim3 ggrid(4, (N + 63) / 64);
    gemm_kernel<<<ggrid, 256>>>(x, Wl, Wr, N);                         // 3 (ncu captures idx 3)

    scan2_kernel<<<1, 64>>>(nb);                                       // 4
    scan3_kernel<<<nb, 1024>>>(N, E);                                  // 5
    fill_kernel<<<592, 256>>>(ei, E, N);                               // 6
    aggregate_kernel<<<N, 128>>>(att, bias, batch, N);                 // 7
    mlp_kernel<<<G, 128>>>(Wm, bm, out);                               // 8
}

// round 11
// speedup vs baseline: 1.4897x; 1.0713x over previous
#include <cuda_runtime.h>

// ---------------------------------------------------------------------------
// GATv2 forward, CSR + fused softmax/aggregate/pool.
//   gemm: 64x64 tile, 4x4/thread, ROW-major A tile padded to pitch 68
//         (banks (4r+k)%32: warp's two rows differ by 4 -> bank delta 16 ->
//         conflict-free), k chunked by 4 with float4 A loads:
//         per-warp smem wavefronts/k drop ~10 -> ~3, below the 16-FFMA issue
//         cost -> fma-bound. (Transposed-A variant measured WORSE: 8-way
//         store conflicts, 115.9us vs 98.1us row-major.)
//   aggregate: BLOCK per dst node (measured 47us faster than warp-per-node).
//   CSR build: hist -> 3-step multiblock scan -> fill.
// Shapes: N=50000, E=800000, D=128, H=4, C=32, HC=128, G=64.
// edge_index / batch_ids arrive as int32 (harness canonicalizes int64).
// ---------------------------------------------------------------------------

#define NMAX   50048
#define EMAX   800000
#define GMAX   256
#define APITCH 68

__device__ float g_xl[(size_t)NMAX * 128];
__device__ float g_xr[(size_t)NMAX * 128];
__device__ int   g_cnt[NMAX];
__device__ int   g_rowptr[NMAX + 1];
__device__ int   g_cursor[NMAX];
__device__ int   g_csrc[EMAX];
__device__ int   g_bsum[64];
__device__ int   g_boff[64];
__device__ float g_pooled[GMAX * 128];

__device__ __forceinline__ int clampi(int v, int lo, int hi) {
    return v < lo ? lo : (v > hi ? hi : v);
}

// ---------------------------------------------------------------------------
__global__ void init_kernel(int n_nodes, int n_pool) {
    int i = blockIdx.x * blockDim.x + threadIdx.x;
    int stride = gridDim.x * blockDim.x;
    for (int idx = i; idx < n_nodes; idx += stride) g_cnt[idx] = 0;
    for (int idx = i; idx < n_pool; idx += stride) g_pooled[idx] = 0.f;
}

// ---------------------------------------------------------------------------
__global__ void hist_kernel(const int* __restrict__ ei, int E, int N) {
    int i = blockIdx.x * blockDim.x + threadIdx.x;
    int stride = gridDim.x * blockDim.x;
    for (int e = i; e < E; e += stride)
        atomicAdd(&g_cnt[clampi(ei[E + e], 0, N - 1)], 1);
}

// scan1: per-1024-chunk block scan; local exclusive prefix + chunk total.
__global__ void __launch_bounds__(1024) scan1_kernel(int N) {
    __shared__ int wsum[32];
    int base = blockIdx.x * 1024;
    int t = threadIdx.x, lane = t & 31, w = t >> 5;
    int v = (base + t < N) ? g_cnt[base + t] : 0;

    int x = v;
#pragma unroll
    for (int off = 1; off < 32; off <<= 1) {
        int y = __shfl_up_sync(0xFFFFFFFFu, x, off);
        if (lane >= off) x += y;
    }
    if (lane == 31) wsum[w] = x;
    __syncthreads();
    if (w == 0) {
        int s = wsum[lane];
#pragma unroll
        for (int off = 1; off < 32; off <<= 1) {
            int y = __shfl_up_sync(0xFFFFFFFFu, s, off);
            if (lane >= off) s += y;
        }
        wsum[lane] = s;
    }
    __syncthreads();

    int excl = x - v + (w > 0 ? wsum[w - 1] : 0);
    if (base + t < N) g_rowptr[base + t] = excl;
    if (t == 1023) g_bsum[blockIdx.x] = excl + v;
}

// scan2: exclusive scan of up to 64 chunk totals.
__global__ void __launch_bounds__(64) scan2_kernel(int nb) {
    __shared__ int s[64];
    int t = threadIdx.x;
    int v = (t < nb) ? g_bsum[t] : 0;
    s[t] = v;
    __syncthreads();
#pragma unroll
    for (int off = 1; off < 64; off <<= 1) {
        int add = (t >= off) ? s[t - off] : 0;
        __syncthreads();
        s[t] += add;
        __syncthreads();
    }
    if (t < nb) g_boff[t] = s[t] - v;
}

// scan3: add chunk offsets; materialize rowptr + cursor.
__global__ void __launch_bounds__(1024) scan3_kernel(int N, int E) {
    int i = blockIdx.x * 1024 + threadIdx.x;
    if (i < N) {
        int r = g_rowptr[i] + g_boff[blockIdx.x];
        g_rowptr[i] = r;
        g_cursor[i] = r;
    }
    if (i == 0) g_rowptr[N] = E;
}

// ---------------------------------------------------------------------------
// GEMM: 64x64 output tile, 4x4/thread, K=128 in 2 K-tiles of 64.
// As row-major with pitch 68 (conflict-free column access across the warp's
// two row-groups); inner loop chunks k by 4: A read = 4x LDS.128 per chunk.
// cb 0,1 -> Wl -> g_xl ; cb 2,3 -> Wr -> g_xr.
// ---------------------------------------------------------------------------
__global__ void __launch_bounds__(256, 4) gemm_kernel(
    const float* __restrict__ x,
    const float* __restrict__ Wl,
    const float* __restrict__ Wr,
    int N)
{
    __shared__ float As[64 * APITCH];   // 17 KB, [row][k] pitch 68
    __shared__ float Bs[64 * 64];       // 16 KB, [k][col]

    int cb   = blockIdx.x;
    int row0 = blockIdx.y * 64;
    const float* W   = (cb < 2) ? Wl : Wr;
    float*       dst = (cb < 2) ? g_xl : g_xr;
    int col0 = (cb & 1) * 64;
    int t = threadIdx.x;
    int tx = t & 15, ty = t >> 4;

    float acc[4][4] = {};

#pragma unroll
    for (int k0 = 0; k0 < 128; k0 += 64) {
        // A tile: float4 gmem load -> float4 smem store, row-major pitch 68.
#pragma unroll
        for (int i = 0; i < 4; i++) {
            int idx = t + i * 256;          // 0..1023
            int r = idx >> 4, c4 = idx & 15;
            float4 v = make_float4(0.f, 0.f, 0.f, 0.f);
            if (row0 + r < N)
                v = *(const float4*)&x[(size_t)(row0 + r) * 128 + k0 + c4 * 4];
            *(float4*)&As[r * APITCH + c4 * 4] = v;
        }
        // B tile: rows k0..k0+63, cols col0..col0+63
#pragma unroll
        for (int i = 0; i < 4; i++) {
            int idx = t + i * 256;
            int k = idx >> 4, j4 = idx & 15;
            *(float4*)&Bs[k * 64 + j4 * 4] = *(const float4*)&W[(k0 + k) * 128 + col0 + j4 * 4];
        }
        __syncthreads();

#pragma unroll
        for (int k = 0; k < 64; k += 4) {
            float4 a0 = *(float4*)&As[(ty * 4 + 0) * APITCH + k];
            float4 a1 = *(float4*)&As[(ty * 4 + 1) * APITCH + k];
            float4 a2 = *(float4*)&As[(ty * 4 + 2) * APITCH + k];
            float4 a3 = *(float4*)&As[(ty * 4 + 3) * APITCH + k];
#pragma unroll
            for (int kk = 0; kk < 4; kk++) {
                float4 b = *(float4*)&Bs[(k + kk) * 64 + tx * 4];
                float va0 = (&a0.x)[kk];
                float va1 = (&a1.x)[kk];
                float va2 = (&a2.x)[kk];
                float va3 = (&a3.x)[kk];
                acc[0][0] += va0 * b.x; acc[0][1] += va0 * b.y; acc[0][2] += va0 * b.z; acc[0][3] += va0 * b.w;
                acc[1][0] += va1 * b.x; acc[1][1] += va1 * b.y; acc[1][2] += va1 * b.z; acc[1][3] += va1 * b.w;
                acc[2][0] += va2 * b.x; acc[2][1] += va2 * b.y; acc[2][2] += va2 * b.z; acc[2][3] += va2 * b.w;
                acc[3][0] += va3 * b.x; acc[3][1] += va3 * b.y; acc[3][2] += va3 * b.z; acc[3][3] += va3 * b.w;
            }
        }
        __syncthreads();
    }

#pragma unroll
    for (int i = 0; i < 4; i++) {
        int row = row0 + ty * 4 + i;
        if (row < N) {
            float4 v = make_float4(acc[i][0], acc[i][1], acc[i][2], acc[i][3]);
            *(float4*)&dst[(size_t)row * 128 + col0 + tx * 4] = v;
        }
    }
}

// ---------------------------------------------------------------------------
__global__ void fill_kernel(const int* __restrict__ ei, int E, int N) {
    int i = blockIdx.x * blockDim.x + threadIdx.x;
    int stride = gridDim.x * blockDim.x;
    for (int e = i; e < E; e += stride) {
        int d = clampi(ei[E + e], 0, N - 1);
        int pos = atomicAdd(&g_cursor[d], 1);
        g_csrc[pos] = clampi(ei[e], 0, N - 1);
    }
}

// ---------------------------------------------------------------------------
// Aggregate: one BLOCK (128 thr = 4 warps) per dst node. Warp h owns head h;
// thread j = h*32+c owns channel c. Softmax without max-shift (logits O(1);
// shift cancels exactly in alpha). Fused bias+relu+atomicMax pooling.
// ---------------------------------------------------------------------------
__device__ __forceinline__ float warp_sum(float v) {
    v += __shfl_xor_sync(0xFFFFFFFFu, v, 16);
    v += __shfl_xor_sync(0xFFFFFFFFu, v, 8);
    v += __shfl_xor_sync(0xFFFFFFFFu, v, 4);
    v += __shfl_xor_sync(0xFFFFFFFFu, v, 2);
    v += __shfl_xor_sync(0xFFFFFFFFu, v, 1);
    return v;
}

__global__ void __launch_bounds__(128) aggregate_kernel(
    const float* __restrict__ att,
    const float* __restrict__ bias,
    const int* __restrict__ batch,
    int N)
{
    int d = blockIdx.x;
    if (d >= N) return;
    int j = threadIdx.x;

    float xr_v  = g_xr[(size_t)d * 128 + j];
    float att_v = att[j];

    // self loop
    float xs = g_xl[(size_t)d * 128 + j];
    float v  = xs + xr_v;
    v = v > 0.f ? v : 0.2f * v;
    float logit = warp_sum(v * att_v);
    float ex    = __expf(logit);
    float denom = ex;
    float acc   = ex * xs;

    int p    = g_rowptr[d];
    int pend = g_rowptr[d + 1];

    for (; p + 1 < pend; p += 2) {
        int s0 = g_csrc[p], s1 = g_csrc[p + 1];
        float x0 = g_xl[(size_t)s0 * 128 + j];
        float x1 = g_xl[(size_t)s1 * 128 + j];
        float v0 = x0 + xr_v; v0 = v0 > 0.f ? v0 : 0.2f * v0;
        float v1 = x1 + xr_v; v1 = v1 > 0.f ? v1 : 0.2f * v1;
        float t0 = v0 * att_v, t1 = v1 * att_v;
#pragma unroll
        for (int m = 16; m >= 1; m >>= 1) {
            t0 += __shfl_xor_sync(0xFFFFFFFFu, t0, m);
            t1 += __shfl_xor_sync(0xFFFFFFFFu, t1, m);
        }
        float e0 = __expf(t0), e1 = __expf(t1);
        denom += e0 + e1;
        acc   += e0 * x0 + e1 * x1;
    }
    if (p < pend) {
        int s0 = g_csrc[p];
        float x0 = g_xl[(size_t)s0 * 128 + j];
        float v0 = x0 + xr_v; v0 = v0 > 0.f ? v0 : 0.2f * v0;
        float t0 = warp_sum(v0 * att_v);
        float e0 = __expf(t0);
        denom += e0;
        acc   += e0 * x0;
    }

    float o = fmaxf(acc / denom + bias[j], 0.f);
    int g = clampi(batch[d], 0, GMAX - 1);
    atomicMax((int*)&g_pooled[g * 128 + j], __float_as_int(o));
}

// ---------------------------------------------------------------------------
__global__ void __launch_bounds__(128) mlp_kernel(
    const float* __restrict__ W,
    const float* __restrict__ b,
    float* __restrict__ out)
{
    __shared__ float pbuf[128];
    int j = threadIdx.x, g = blockIdx.x;
    pbuf[j] = g_pooled[g * 128 + j];
    __syncthreads();
    float acc = b[j];
#pragma unroll 8
    for (int k = 0; k < 128; k++)
        acc += pbuf[k] * W[k * 128 + j];
    out[g * 128 + j] = fmaxf(acc, 0.f);
}

// ---------------------------------------------------------------------------
extern "C" void kernel_launch(void* const* d_in, const int* in_sizes, int n_in,
                              void* d_out, int out_size)
{
    const float* x     = (const float*)d_in[0];
    const int*   ei    = (const int*)d_in[1];
    const int*   batch = (const int*)d_in[2];
    int base = (n_in >= 10) ? 4 : 3;
    const float* Wl   = (const float*)d_in[base + 0];
    const float* Wr   = (const float*)d_in[base + 1];
    const float* att  = (const float*)d_in[base + 2];
    const float* bias = (const float*)d_in[base + 3];
    const float* Wm   = (const float*)d_in[base + 4];
    const float* bm   = (const float*)d_in[base + 5];

    int N = in_sizes[0] / 128;
    int E = in_sizes[1] / 2;
    int G = out_size / 128;
    float* out = (float*)d_out;
    int nb = (N + 1023) / 1024;

    init_kernel<<<(N + 255) / 256, 256>>>(N, G * 128);                 // 0
    hist_kernel<<<592, 256>>>(ei, E, N);                               // 1
    scan1_kernel<<<nb, 1024>>>(N);                                     // 2

    dim3 ggrid(4, (N + 63) / 64);
    gemm_kernel<<<ggrid, 256>>>(x, Wl, Wr, N);                         // 3 (ncu captures idx 3)

    scan2_kernel<<<1, 64>>>(nb);                                       // 4
    scan3_kernel<<<nb, 1024>>>(N, E);                                  // 5
    fill_kernel<<<592, 256>>>(ei, E, N);                               // 6
    aggregate_kernel<<<N, 128>>>(att, bias, batch, N);                 // 7
    mlp_kernel<<<G, 128>>>(Wm, bm, out);                               // 8
}

// round 12
// speedup vs baseline: 1.6281x; 1.0929x over previous
#include <cuda_runtime.h>
#include <cstdint>

// ---------------------------------------------------------------------------
// GATv2 forward, CSR + fused softmax/aggregate/pool.
//   gemm: TENSOR-CORE 3xTF32 (mma.sync.m16n8k8.tf32). FFMA version was pinned
//         at 98us across 3 inner-loop restructurings (issue-slot bound);
//         3xTF32 keeps ~fp32 accuracy: a_hi*b_hi + a_hi*b_lo + a_lo*b_hi.
//         W pre-split to smem hi/lo (pitch 136: fragment banks 8*tig+g
//         conflict-free); A fp32 in smem (pitch 36: banks 4g+tig), split
//         on the fly. 64x128 block tile, 8 warps x (16x64).
//   aggregate: BLOCK per dst node (measured 47us faster than warp-per-node).
//   CSR build: hist -> 3-step multiblock scan -> fill.
// Shapes: N=50000, E=800000, D=128, H=4, C=32, HC=128, G=64.
// edge_index / batch_ids arrive as int32 (harness canonicalizes int64).
// ---------------------------------------------------------------------------

#define NMAX   50048
#define EMAX   800000
#define GMAX   256

__device__ float g_xl[(size_t)NMAX * 128];
__device__ float g_xr[(size_t)NMAX * 128];
__device__ int   g_cnt[NMAX];
__device__ int   g_rowptr[NMAX + 1];
__device__ int   g_cursor[NMAX];
__device__ int   g_csrc[EMAX];
__device__ int   g_bsum[64];
__device__ int   g_boff[64];
__device__ float g_pooled[GMAX * 128];

__device__ __forceinline__ int clampi(int v, int lo, int hi) {
    return v < lo ? lo : (v > hi ? hi : v);
}

// ---------------------------------------------------------------------------
__global__ void init_kernel(int n_nodes, int n_pool) {
    int i = blockIdx.x * blockDim.x + threadIdx.x;
    int stride = gridDim.x * blockDim.x;
    for (int idx = i; idx < n_nodes; idx += stride) g_cnt[idx] = 0;
    for (int idx = i; idx < n_pool; idx += stride) g_pooled[idx] = 0.f;
}

// ---------------------------------------------------------------------------
__global__ void hist_kernel(const int* __restrict__ ei, int E, int N) {
    int i = blockIdx.x * blockDim.x + threadIdx.x;
    int stride = gridDim.x * blockDim.x;
    for (int e = i; e < E; e += stride)
        atomicAdd(&g_cnt[clampi(ei[E + e], 0, N - 1)], 1);
}

// scan1: per-1024-chunk block scan; local exclusive prefix + chunk total.
__global__ void __launch_bounds__(1024) scan1_kernel(int N) {
    __shared__ int wsum[32];
    int base = blockIdx.x * 1024;
    int t = threadIdx.x, lane = t & 31, w = t >> 5;
    int v = (base + t < N) ? g_cnt[base + t] : 0;

    int x = v;
#pragma unroll
    for (int off = 1; off < 32; off <<= 1) {
        int y = __shfl_up_sync(0xFFFFFFFFu, x, off);
        if (lane >= off) x += y;
    }
    if (lane == 31) wsum[w] = x;
    __syncthreads();
    if (w == 0) {
        int s = wsum[lane];
#pragma unroll
        for (int off = 1; off < 32; off <<= 1) {
            int y = __shfl_up_sync(0xFFFFFFFFu, s, off);
            if (lane >= off) s += y;
        }
        wsum[lane] = s;
    }
    __syncthreads();

    int excl = x - v + (w > 0 ? wsum[w - 1] : 0);
    if (base + t < N) g_rowptr[base + t] = excl;
    if (t == 1023) g_bsum[blockIdx.x] = excl + v;
}

// scan2: exclusive scan of up to 64 chunk totals.
__global__ void __launch_bounds__(64) scan2_kernel(int nb) {
    __shared__ int s[64];
    int t = threadIdx.x;
    int v = (t < nb) ? g_bsum[t] : 0;
    s[t] = v;
    __syncthreads();
#pragma unroll
    for (int off = 1; off < 64; off <<= 1) {
        int add = (t >= off) ? s[t - off] : 0;
        __syncthreads();
        s[t] += add;
        __syncthreads();
    }
    if (t < nb) g_boff[t] = s[t] - v;
}

// scan3: add chunk offsets; materialize rowptr + cursor.
__global__ void __launch_bounds__(1024) scan3_kernel(int N, int E) {
    int i = blockIdx.x * 1024 + threadIdx.x;
    if (i < N) {
        int r = g_rowptr[i] + g_boff[blockIdx.x];
        g_rowptr[i] = r;
        g_cursor[i] = r;
    }
    if (i == 0) g_rowptr[N] = E;
}

// ---------------------------------------------------------------------------
// 3xTF32 tensor-core GEMM.
// Block: 64 rows x 128 cols (full HC) of (x @ W); grid.x selects Wl/Wr.
// 8 warps: wm = warp&3 (16-row m-tile), wn = warp>>2 (64-col n-half).
// K staged in chunks of 32: As fp32 [64][pitch36], Bh/Bl tf32 [32][pitch136].
// mma.m16n8k8.row.col: per warp 8 n-tiles, 3 MMAs each per k-step.
// ---------------------------------------------------------------------------
#define AP 36
#define BP 136

__device__ __forceinline__ uint32_t f2tf(float f) {
    uint32_t r;
    asm("cvt.rna.tf32.f32 %0, %1;" : "=r"(r) : "f"(f));
    return r;
}

__device__ __forceinline__ void mma_tf32(float* c, const uint32_t* a,
                                         uint32_t b0, uint32_t b1) {
    asm volatile(
        "mma.sync.aligned.m16n8k8.row.col.f32.tf32.tf32.f32 "
        "{%0,%1,%2,%3}, {%4,%5,%6,%7}, {%8,%9}, {%0,%1,%2,%3};"
        : "+f"(c[0]), "+f"(c[1]), "+f"(c[2]), "+f"(c[3])
        : "r"(a[0]), "r"(a[1]), "r"(a[2]), "r"(a[3]), "r"(b0), "r"(b1));
}

__global__ void __launch_bounds__(256) gemm_kernel(
    const float* __restrict__ x,
    const float* __restrict__ Wl,
    const float* __restrict__ Wr,
    int N)
{
    __shared__ float    As[64 * AP];       // 9.2 KB
    __shared__ uint32_t Bh[32 * BP];       // 17.4 KB
    __shared__ uint32_t Bl[32 * BP];       // 17.4 KB

    int cb   = blockIdx.x;
    int row0 = blockIdx.y * 64;
    const float* W   = cb ? Wr : Wl;
    float*       dst = cb ? g_xr : g_xl;

    int t    = threadIdx.x;
    int w    = t >> 5, lane = t & 31;
    int wm   = w & 3, wn = w >> 2;
    int g    = lane >> 2, tig = lane & 3;

    float c[8][4];
#pragma unroll
    for (int j = 0; j < 8; j++)
#pragma unroll
        for (int i = 0; i < 4; i++) c[j][i] = 0.f;

#pragma unroll
    for (int k0 = 0; k0 < 128; k0 += 32) {
        // stage A: 64 rows x 32 cols fp32
#pragma unroll
        for (int i = 0; i < 2; i++) {
            int idx = t + i * 256;            // 0..511 over 64x8 float4
            int r = idx >> 3, c4 = idx & 7;
            float4 v = make_float4(0.f, 0.f, 0.f, 0.f);
            if (row0 + r < N)
                v = *(const float4*)&x[(size_t)(row0 + r) * 128 + k0 + c4 * 4];
            *(float4*)&As[r * AP + c4 * 4] = v;
        }
        // stage B hi/lo: 32 k-rows x 128 cols
#pragma unroll
        for (int i = 0; i < 4; i++) {
            int idx = t + i * 256;            // 0..1023 over 32x32 float4
            int k = idx >> 5, j4 = idx & 31;
            float4 v = *(const float4*)&W[(size_t)(k0 + k) * 128 + j4 * 4];
            uint32_t h0 = f2tf(v.x), h1 = f2tf(v.y), h2 = f2tf(v.z), h3 = f2tf(v.w);
            int base = k * BP + j4 * 4;
            Bh[base + 0] = h0; Bh[base + 1] = h1; Bh[base + 2] = h2; Bh[base + 3] = h3;
            Bl[base + 0] = f2tf(v.x - __uint_as_float(h0));
            Bl[base + 1] = f2tf(v.y - __uint_as_float(h1));
            Bl[base + 2] = f2tf(v.z - __uint_as_float(h2));
            Bl[base + 3] = f2tf(v.w - __uint_as_float(h3));
        }
        __syncthreads();

#pragma unroll
        for (int ks = 0; ks < 32; ks += 8) {
            // A fragment (m16k8, row-major) + on-the-fly hi/lo split
            float a0f = As[(wm * 16 + g)     * AP + ks + tig];
            float a1f = As[(wm * 16 + g + 8) * AP + ks + tig];
            float a2f = As[(wm * 16 + g)     * AP + ks + tig + 4];
            float a3f = As[(wm * 16 + g + 8) * AP + ks + tig + 4];
            uint32_t ah[4], al[4];
            ah[0] = f2tf(a0f); al[0] = f2tf(a0f - __uint_as_float(ah[0]));
            ah[1] = f2tf(a1f); al[1] = f2tf(a1f - __uint_as_float(ah[1]));
            ah[2] = f2tf(a2f); al[2] = f2tf(a2f - __uint_as_float(ah[2]));
            ah[3] = f2tf(a3f); al[3] = f2tf(a3f - __uint_as_float(ah[3]));

#pragma unroll
            for (int j = 0; j < 8; j++) {
                int col = wn * 64 + j * 8 + g;
                uint32_t bh0 = Bh[(ks + tig)     * BP + col];
                uint32_t bh1 = Bh[(ks + tig + 4) * BP + col];
                uint32_t bl0 = Bl[(ks + tig)     * BP + col];
                uint32_t bl1 = Bl[(ks + tig + 4) * BP + col];
                mma_tf32(c[j], ah, bl0, bl1);   // a_hi * b_lo
                mma_tf32(c[j], al, bh0, bh1);   // a_lo * b_hi
                mma_tf32(c[j], ah, bh0, bh1);   // a_hi * b_hi
            }
        }
        __syncthreads();
    }

    // epilogue: c[j][{0,1}] -> (row, col..col+1), c[j][{2,3}] -> (row+8, ..)
#pragma unroll
    for (int j = 0; j < 8; j++) {
        int col = wn * 64 + j * 8 + tig * 2;
        int r0  = row0 + wm * 16 + g;
        if (r0 < N)
            *(float2*)&dst[(size_t)r0 * 128 + col] = make_float2(c[j][0], c[j][1]);
        int r1 = r0 + 8;
        if (r1 < N)
            *(float2*)&dst[(size_t)r1 * 128 + col] = make_float2(c[j][2], c[j][3]);
    }
}

// ---------------------------------------------------------------------------
__global__ void fill_kernel(const int* __restrict__ ei, int E, int N) {
    int i = blockIdx.x * blockDim.x + threadIdx.x;
    int stride = gridDim.x * blockDim.x;
    for (int e = i; e < E; e += stride) {
        int d = clampi(ei[E + e], 0, N - 1);
        int pos = atomicAdd(&g_cursor[d], 1);
        g_csrc[pos] = clampi(ei[e], 0, N - 1);
    }
}

// ---------------------------------------------------------------------------
// Aggregate: one BLOCK (128 thr = 4 warps) per dst node. Warp h owns head h;
// thread j = h*32+c owns channel c. Softmax without max-shift (logits O(1);
// shift cancels exactly in alpha). Fused bias+relu+atomicMax pooling.
// ---------------------------------------------------------------------------
__device__ __forceinline__ float warp_sum(float v) {
    v += __shfl_xor_sync(0xFFFFFFFFu, v, 16);
    v += __shfl_xor_sync(0xFFFFFFFFu, v, 8);
    v += __shfl_xor_sync(0xFFFFFFFFu, v, 4);
    v += __shfl_xor_sync(0xFFFFFFFFu, v, 2);
    v += __shfl_xor_sync(0xFFFFFFFFu, v, 1);
    return v;
}

__global__ void __launch_bounds__(128) aggregate_kernel(
    const float* __restrict__ att,
    const float* __restrict__ bias,
    const int* __restrict__ batch,
    int N)
{
    int d = blockIdx.x;
    if (d >= N) return;
    int j = threadIdx.x;

    float xr_v  = g_xr[(size_t)d * 128 + j];
    float att_v = att[j];

    // self loop
    float xs = g_xl[(size_t)d * 128 + j];
    float v  = xs + xr_v;
    v = v > 0.f ? v : 0.2f * v;
    float logit = warp_sum(v * att_v);
    float ex    = __expf(logit);
    float denom = ex;
    float acc   = ex * xs;

    int p    = g_rowptr[d];
    int pend = g_rowptr[d + 1];

    for (; p + 1 < pend; p += 2) {
        int s0 = g_csrc[p], s1 = g_csrc[p + 1];
        float x0 = g_xl[(size_t)s0 * 128 + j];
        float x1 = g_xl[(size_t)s1 * 128 + j];
        float v0 = x0 + xr_v; v0 = v0 > 0.f ? v0 : 0.2f * v0;
        float v1 = x1 + xr_v; v1 = v1 > 0.f ? v1 : 0.2f * v1;
        float t0 = v0 * att_v, t1 = v1 * att_v;
#pragma unroll
        for (int m = 16; m >= 1; m >>= 1) {
            t0 += __shfl_xor_sync(0xFFFFFFFFu, t0, m);
            t1 += __shfl_xor_sync(0xFFFFFFFFu, t1, m);
        }
        float e0 = __expf(t0), e1 = __expf(t1);
        denom += e0 + e1;
        acc   += e0 * x0 + e1 * x1;
    }
    if (p < pend) {
        int s0 = g_csrc[p];
        float x0 = g_xl[(size_t)s0 * 128 + j];
        float v0 = x0 + xr_v; v0 = v0 > 0.f ? v0 : 0.2f * v0;
        float t0 = warp_sum(v0 * att_v);
        float e0 = __expf(t0);
        denom += e0;
        acc   += e0 * x0;
    }

    float o = fmaxf(acc / denom + bias[j], 0.f);
    int g = clampi(batch[d], 0, GMAX - 1);
    atomicMax((int*)&g_pooled[g * 128 + j], __float_as_int(o));
}

// ---------------------------------------------------------------------------
__global__ void __launch_bounds__(128) mlp_kernel(
    const float* __restrict__ W,
    const float* __restrict__ b,
    float* __restrict__ out)
{
    __shared__ float pbuf[128];
    int j = threadIdx.x, g = blockIdx.x;
    pbuf[j] = g_pooled[g * 128 + j];
    __syncthreads();
    float acc = b[j];
#pragma unroll 8
    for (int k = 0; k < 128; k++)
        acc += pbuf[k] * W[k * 128 + j];
    out[g * 128 + j] = fmaxf(acc, 0.f);
}

// ---------------------------------------------------------------------------
extern "C" void kernel_launch(void* const* d_in, const int* in_sizes, int n_in,
                              void* d_out, int out_size)
{
    const float* x     = (const float*)d_in[0];
    const int*   ei    = (const int*)d_in[1];
    const int*   batch = (const int*)d_in[2];
    int base = (n_in >= 10) ? 4 : 3;
    const float* Wl   = (const float*)d_in[base + 0];
    const float* Wr   = (const float*)d_in[base + 1];
    const float* att  = (const float*)d_in[base + 2];
    const float* bias = (const float*)d_in[base + 3];
    const float* Wm   = (const float*)d_in[base + 4];
    const float* bm   = (const float*)d_in[base + 5];

    int N = in_sizes[0] / 128;
    int E = in_sizes[1] / 2;
    int G = out_size / 128;
    float* out = (float*)d_out;
    int nb = (N + 1023) / 1024;

    init_kernel<<<(N + 255) / 256, 256>>>(N, G * 128);                 // 0
    hist_kernel<<<592, 256>>>(ei, E, N);                               // 1
    scan1_kernel<<<nb, 1024>>>(N);                                     // 2

    dim3 ggrid(2, (N + 63) / 64);
    gemm_kernel<<<ggrid, 256>>>(x, Wl, Wr, N);                         // 3 (ncu captures idx 3)

    scan2_kernel<<<1, 64>>>(nb);                                       // 4
    scan3_kernel<<<nb, 1024>>>(N, E);                                  // 5
    fill_kernel<<<592, 256>>>(ei, E, N);                               // 6
    aggregate_kernel<<<N, 128>>>(att, bias, batch, N);                 // 7
    mlp_kernel<<<G, 128>>>(Wm, bm, out);                               // 8
}